// round 16
// baseline (speedup 1.0000x reference)
#include <cuda_runtime.h>
#include <cstdint>

#define NQ       50000
#define MNB      32
#define NKP      15
#define DIN      64
#define DOUT     64
#define OD       45
#define ODP      48
#define KD       960
#define KDP      962         // padded WF row stride (conflict-free q-spread reads)
#define QPB      8
#define NTHREADS 256
#define KSLICE   120         // k per warp slice (8 warps cover 960)

// ---------------- shared memory layout (floats) ----------------
#define SM_WF  0                        // QPB*KDP = 7696
#define SM_OF  (SM_WF + QPB*KDP)        // QPB*ODP = 384
#define SM_KP  (SM_OF + QPB*ODP)        // 48
#define SM_DK  (SM_KP + ODP)            // QPB*ODP = 384
#define SM_OV  (SM_DK + QPB*ODP)        // overlay: AW 5120 / P2 3200 / P4 4224
#define SM_AW  SM_OV
#define SM_P2  SM_OV
#define SM_P4  SM_OV
#define SM_TOT (SM_OV + 5120)
#define SMEM_BYTES (SM_TOT*4)           // 54,528 B -> 3 blocks/SM
#define P2ROW  50                       // P2 row stride
#define P4ROW  66                       // P4 row stride

// zero-padded offset weights [960][48]
__device__ float g_owpad[KD*ODP];

__global__ void prep_owpad(const float* __restrict__ ow)
{
    int i = blockIdx.x*blockDim.x + threadIdx.x;
    if (i < KD*ODP) {
        int kk = i / ODP, e = i - kk*ODP;
        g_owpad[i] = (e < OD) ? ow[kk*OD + e] : 0.0f;
    }
}

__device__ __forceinline__ uint64_t ffma2(uint64_t a, uint64_t b, uint64_t c)
{
    uint64_t d;
    asm("fma.rn.f32x2 %0, %1, %2, %3;" : "=l"(d) : "l"(a), "l"(b), "l"(c));
    return d;
}
__device__ __forceinline__ uint64_t dup2(float v)
{
    uint64_t d;
    asm("mov.b64 %0, {%1, %1};" : "=l"(d) : "f"(v));
    return d;
}
__device__ __forceinline__ uint64_t pack2(float a, float b)
{
    uint64_t d;
    asm("mov.b64 %0, {%1, %2};" : "=l"(d) : "f"(a), "f"(b));
    return d;
}
__device__ __forceinline__ float lo32(uint64_t v) { return __uint_as_float((uint32_t)v); }
__device__ __forceinline__ float hi32(uint64_t v) { return __uint_as_float((uint32_t)(v >> 32)); }

// Aggregation for query q == warp. Lane owns channel pair (2l, 2l+1).
// K-pair FFMA2 packing: aw non-dup (16 vals, row stride 20 floats = 80B, 16B-aligned).
// Per neighbor: 4 broadcast LDS.128 + 1 LDG.64 + 2 dup movs + 16 FFMA2.
__device__ __forceinline__ void kp_aggregate(
    float* sm, int warp, int lane,
    float nbx, float nby, float nbz, int ni,
    const float* kpp,
    const float* __restrict__ x)
{
    float* awr = sm + SM_AW + warp*640 + lane*20;
    {
        float wv[16];
#pragma unroll
        for (int k = 0; k < NKP; k++) {
            float dx = nbx - kpp[3*k+0];
            float dy = nby - kpp[3*k+1];
            float dz = nbz - kpp[3*k+2];
            float d  = sqrtf(fmaf(dx, dx, fmaf(dy, dy, dz*dz)));
            wv[k] = fmaxf(1.0f - d, 0.0f);
        }
        wv[15] = 0.0f;
        *(float4*)(awr + 0)  = make_float4(wv[0],  wv[1],  wv[2],  wv[3]);
        *(float4*)(awr + 4)  = make_float4(wv[4],  wv[5],  wv[6],  wv[7]);
        *(float4*)(awr + 8)  = make_float4(wv[8],  wv[9],  wv[10], wv[11]);
        *(float4*)(awr + 12) = make_float4(wv[12], wv[13], wv[14], wv[15]);
    }
    __syncwarp();

    uint64_t ac0[8], ac1[8];   // k-pair accumulators for channels c0, c1
#pragma unroll
    for (int kp = 0; kp < 8; kp++) { ac0[kp] = 0ull; ac1[kp] = 0ull; }

    const float* awb = sm + SM_AW + warp*640;

#pragma unroll 4
    for (int m = 0; m < MNB; m++) {
        int n = __shfl_sync(0xffffffffu, ni, m);
        float2 f = *(const float2*)(x + n*DIN + 2*lane);   // LDG.64, coalesced
        uint64_t d0 = dup2(f.x), d1 = dup2(f.y);
        const ulonglong2* ar = (const ulonglong2*)(awb + m*20);  // 4 broadcast LDS.128
        {
            ulonglong2 a0 = ar[0], a1 = ar[1];
            ac0[0] = ffma2(a0.x, d0, ac0[0]);  ac1[0] = ffma2(a0.x, d1, ac1[0]);
            ac0[1] = ffma2(a0.y, d0, ac0[1]);  ac1[1] = ffma2(a0.y, d1, ac1[1]);
            ac0[2] = ffma2(a1.x, d0, ac0[2]);  ac1[2] = ffma2(a1.x, d1, ac1[2]);
            ac0[3] = ffma2(a1.y, d0, ac0[3]);  ac1[3] = ffma2(a1.y, d1, ac1[3]);
        }
        {
            ulonglong2 a2 = ar[2], a3 = ar[3];
            ac0[4] = ffma2(a2.x, d0, ac0[4]);  ac1[4] = ffma2(a2.x, d1, ac1[4]);
            ac0[5] = ffma2(a2.y, d0, ac0[5]);  ac1[5] = ffma2(a2.y, d1, ac1[5]);
            ac0[6] = ffma2(a3.x, d0, ac0[6]);  ac1[6] = ffma2(a3.x, d1, ac1[6]);
            ac0[7] = ffma2(a3.y, d0, ac0[7]);  ac1[7] = ffma2(a3.y, d1, ac1[7]);
        }
    }

    // repack to WF[q][k] with row stride KDP (STS.64 conflict-free)
    float* wr = sm + SM_WF + warp*KDP;
#pragma unroll
    for (int kp = 0; kp < 7; kp++) {
        *(uint64_t*)(wr + (2*kp)*DIN   + 2*lane) = pack2(lo32(ac0[kp]), lo32(ac1[kp]));
        *(uint64_t*)(wr + (2*kp+1)*DIN + 2*lane) = pack2(hi32(ac0[kp]), hi32(ac1[kp]));
    }
    *(uint64_t*)(wr + 14*DIN + 2*lane) = pack2(lo32(ac0[7]), lo32(ac1[7]));
}

__global__ __launch_bounds__(NTHREADS, 3)
void kpconv_deform_fused(
    const float* __restrict__ qp,    // [N,3]
    const float* __restrict__ sp,    // [N,3]
    const int*   __restrict__ neigh, // [N,32]
    const float* __restrict__ x,     // [N,64]
    const float* __restrict__ kpts,  // [15,3]
    const float* __restrict__ obias, // [45]
    const float* __restrict__ w,     // [960,64]
    float*       __restrict__ out)   // [N,64]
{
    extern __shared__ float sm[];
    const int tid  = threadIdx.x;
    const int lane = tid & 31;
    const int warp = tid >> 5;
    const int qg   = lane & 7;        // GEMM: query slot
    const int cg   = lane >> 3;       // GEMM: channel group 0..3
    const int q0   = blockIdx.x * QPB;
    const int q    = q0 + warp;

    if (tid < OD) sm[SM_KP + tid] = kpts[tid];

    // neighbor geometry, registers only (lane = its own neighbor m)
    float qx = qp[q*3+0], qy = qp[q*3+1], qz = qp[q*3+2];
    int   ni = neigh[q*MNB + lane];
    float nbx = sp[ni*3+0] - qx;
    float nby = sp[ni*3+1] - qy;
    float nbz = sp[ni*3+2] - qz;
    __syncthreads();

    // -------- Phase 1: rigid aggregation -> WF1 --------
    kp_aggregate(sm, warp, lane, nbx, nby, nbz, ni, sm + SM_KP, x);
    __syncthreads();

    // -------- Phase 2: offset GEMM  OF[8][48] = WF1[8][960] @ OWpad[960][48] --------
    // Lane = (qg, cg); thread owns channels [12*cg, 12*cg+12) for query qg,
    // accumulating over this warp's 120-k slice. Feature via q-spread LDS.32.
    {
        const int kk0 = warp * KSLICE;
        const int c0  = 12 * cg;
        uint64_t ac[6];
#pragma unroll
        for (int t = 0; t < 6; t++) ac[t] = 0ull;
        const float* fb = sm + SM_WF + qg*KDP;
        const float* wb = g_owpad + c0;
#pragma unroll 4
        for (int kk = kk0; kk < kk0 + KSLICE; kk++) {
            uint64_t d = dup2(fb[kk]);                         // LDS.32 q-spread + dup
            const ulonglong2* wr = (const ulonglong2*)(wb + kk*ODP);
            ulonglong2 w01 = wr[0];
            uint64_t   w2  = ((const uint64_t*)wr)[2];
            float4     w3f = *(const float4*)(wb + kk*ODP + 8);  // hmm avoid; use direct:
            (void)w3f;
            ac[0] = ffma2(d, w01.x, ac[0]);
            ac[1] = ffma2(d, w01.y, ac[1]);
            ac[2] = ffma2(d, w2,    ac[2]);
            uint64_t w3 = ((const uint64_t*)wr)[3];
            uint64_t w4 = ((const uint64_t*)wr)[4];
            uint64_t w5 = ((const uint64_t*)wr)[5];
            ac[3] = ffma2(d, w3, ac[3]);
            ac[4] = ffma2(d, w4, ac[4]);
            ac[5] = ffma2(d, w5, ac[5]);
        }
        __syncthreads();   // AW reads (phase 1) done before P2 overlay stores
        float* pr = sm + SM_P2 + warp*(QPB*P2ROW) + qg*P2ROW + c0;
#pragma unroll
        for (int t = 0; t < 6; t++)
            *(uint64_t*)(pr + 2*t) = ac[t];
    }
    __syncthreads();

    // reduce 8 warp-slices -> OF (+bias)
    if (tid < 192) {
        int qi = tid / 24, ep = tid % 24, e = 2*ep;
        float sx = 0.f, sy = 0.f;
#pragma unroll
        for (int s = 0; s < 8; s++) {
            float2 p = *(const float2*)(sm + SM_P2 + s*(QPB*P2ROW) + qi*P2ROW + e);
            sx += p.x; sy += p.y;
        }
        sx += (e   < OD) ? obias[e]   : 0.f;
        sy += (e+1 < OD) ? obias[e+1] : 0.f;
        *(float2*)(sm + SM_OF + qi*ODP + e) = make_float2(sx, sy);
    }
    __syncthreads();

    // -------- Phase 3: deformed kernel points + aggregation -> WF2 --------
    for (int t2 = lane; t2 < OD; t2 += 32)
        sm[SM_DK + warp*ODP + t2] = sm[SM_KP + t2] + sm[SM_OF + warp*ODP + t2];
    __syncwarp();
    kp_aggregate(sm, warp, lane, nbx, nby, nbz, ni, sm + SM_DK + warp*ODP, x);
    __syncthreads();

    // -------- Phase 4: output GEMM  out[8][64] = WF2[8][960] @ W[960][64] --------
    // Thread owns channels [16*cg, 16*cg+16) for query qg over 120-k slice.
    {
        const int kk0 = warp * KSLICE;
        const int c0  = 16 * cg;
        uint64_t ac[8];
#pragma unroll
        for (int t = 0; t < 8; t++) ac[t] = 0ull;
        const float* fb = sm + SM_WF + qg*KDP;
        const float* wb = w + c0;
#pragma unroll 4
        for (int kk = kk0; kk < kk0 + KSLICE; kk++) {
            uint64_t d = dup2(fb[kk]);
            const uint64_t* wr = (const uint64_t*)(wb + kk*DOUT);
            ac[0] = ffma2(d, wr[0], ac[0]);
            ac[1] = ffma2(d, wr[1], ac[1]);
            ac[2] = ffma2(d, wr[2], ac[2]);
            ac[3] = ffma2(d, wr[3], ac[3]);
            ac[4] = ffma2(d, wr[4], ac[4]);
            ac[5] = ffma2(d, wr[5], ac[5]);
            ac[6] = ffma2(d, wr[6], ac[6]);
            ac[7] = ffma2(d, wr[7], ac[7]);
        }
        __syncthreads();   // AW reads (phase 3) done before P4 overlay stores
        float* pr = sm + SM_P4 + warp*(QPB*P4ROW) + qg*P4ROW + c0;
#pragma unroll
        for (int t = 0; t < 8; t++)
            *(uint64_t*)(pr + 2*t) = ac[t];
    }
    __syncthreads();

    // reduce 8 warp-slices -> global out
    {
        int qi = tid >> 5, e = (tid & 31) * 2;
        float sx = 0.f, sy = 0.f;
#pragma unroll
        for (int s = 0; s < 8; s++) {
            float2 p = *(const float2*)(sm + SM_P4 + s*(QPB*P4ROW) + qi*P4ROW + e);
            sx += p.x; sy += p.y;
        }
        *(float2*)(out + (q0 + qi)*DOUT + e) = make_float2(sx, sy);
    }
}

extern "C" void kernel_launch(void* const* d_in, const int* in_sizes, int n_in,
                              void* d_out, int out_size)
{
    const float* qp    = (const float*)d_in[0];
    const float* sp    = (const float*)d_in[1];
    const int*   neigh = (const int*)  d_in[2];
    const float* x     = (const float*)d_in[3];
    const float* kpts  = (const float*)d_in[4];
    const float* ow    = (const float*)d_in[5];
    const float* obias = (const float*)d_in[6];
    const float* w     = (const float*)d_in[7];
    float* out = (float*)d_out;

    prep_owpad<<<(KD*ODP + 255)/256, 256>>>(ow);

    cudaFuncSetAttribute(kpconv_deform_fused,
                         cudaFuncAttributeMaxDynamicSharedMemorySize, SMEM_BYTES);

    kpconv_deform_fused<<<NQ/QPB, NTHREADS, SMEM_BYTES>>>(
        qp, sp, neigh, x, kpts, obias, w, out);
}

// round 17
// speedup vs baseline: 1.7890x; 1.7890x over previous
#include <cuda_runtime.h>
#include <cstdint>

#define NQ       50000
#define MNB      32
#define NKP      15
#define DIN      64
#define DOUT     64
#define OD       45
#define ODP      48
#define KD       960
#define QPB      8
#define NTHREADS 256
#define KSL      60          // k per GEMM slice; 16 slices cover KD

// ---------------- shared memory layout (floats) ----------------
#define SM_WF  0                        // QPB*KD = 7680 (non-dup features)
#define SM_OF  (SM_WF + QPB*KD)         // QPB*ODP = 384
#define SM_KP  (SM_OF + QPB*ODP)        // 48
#define SM_DK  (SM_KP + ODP)            // QPB*ODP = 384
#define SM_OV  (SM_DK + QPB*ODP)        // overlay: AW 6144 / P2 6144 / P4 8192
#define SM_AW  SM_OV
#define SM_P2  SM_OV
#define SM_P4  SM_OV
#define SM_TOT (SM_OV + 8192)
#define SMEM_BYTES (SM_TOT*4)           // 66,752 B -> 3 blocks/SM

// zero-padded offset weights [960][48]
__device__ float g_owpad[KD*ODP];

__global__ void prep_owpad(const float* __restrict__ ow)
{
    int i = blockIdx.x*blockDim.x + threadIdx.x;
    if (i < KD*ODP) {
        int kk = i / ODP, e = i - kk*ODP;
        g_owpad[i] = (e < OD) ? ow[kk*OD + e] : 0.0f;
    }
}

__device__ __forceinline__ uint64_t ffma2(uint64_t a, uint64_t b, uint64_t c)
{
    uint64_t d;
    asm("fma.rn.f32x2 %0, %1, %2, %3;" : "=l"(d) : "l"(a), "l"(b), "l"(c));
    return d;
}
__device__ __forceinline__ uint64_t dup2(float v)
{
    uint64_t d;
    asm("mov.b64 %0, {%1, %1};" : "=l"(d) : "f"(v));
    return d;
}
__device__ __forceinline__ uint64_t pack2(float a, float b)
{
    uint64_t d;
    asm("mov.b64 %0, {%1, %2};" : "=l"(d) : "f"(a), "f"(b));
    return d;
}
__device__ __forceinline__ float lo32(uint64_t v) { return __uint_as_float((uint32_t)v); }
__device__ __forceinline__ float hi32(uint64_t v) { return __uint_as_float((uint32_t)(v >> 32)); }

// Aggregation for query q == warp. Lane owns channel pair (2l, 2l+1).
// K-pair FFMA2 packing: aw non-dup (16 vals, row stride 24 floats = 96B, 16B-aligned).
// Per neighbor: 4 broadcast LDS.128 + 1 LDG.64 + 2 dup movs + 16 FFMA2.
// m-loop unrolled 8 deep for gather-latency hiding (MLP ~8).
__device__ __forceinline__ void kp_aggregate(
    float* sm, int warp, int lane,
    float nbx, float nby, float nbz, int ni,
    const float* kpp,
    const float* __restrict__ x)
{
    float* awr = sm + SM_AW + warp*768 + lane*24;
    {
        float wv[16];
#pragma unroll
        for (int k = 0; k < NKP; k++) {
            float dx = nbx - kpp[3*k+0];
            float dy = nby - kpp[3*k+1];
            float dz = nbz - kpp[3*k+2];
            float d  = sqrtf(fmaf(dx, dx, fmaf(dy, dy, dz*dz)));
            wv[k] = fmaxf(1.0f - d, 0.0f);
        }
        wv[15] = 0.0f;
        *(float4*)(awr + 0)  = make_float4(wv[0],  wv[1],  wv[2],  wv[3]);
        *(float4*)(awr + 4)  = make_float4(wv[4],  wv[5],  wv[6],  wv[7]);
        *(float4*)(awr + 8)  = make_float4(wv[8],  wv[9],  wv[10], wv[11]);
        *(float4*)(awr + 12) = make_float4(wv[12], wv[13], wv[14], wv[15]);
    }
    __syncwarp();

    uint64_t ac0[8], ac1[8];   // k-pair accumulators for channels c0, c1
#pragma unroll
    for (int kp = 0; kp < 8; kp++) { ac0[kp] = 0ull; ac1[kp] = 0ull; }

    const float* awb = sm + SM_AW + warp*768;

#pragma unroll 8
    for (int m = 0; m < MNB; m++) {
        int n = __shfl_sync(0xffffffffu, ni, m);
        float2 f = *(const float2*)(x + n*DIN + 2*lane);   // LDG.64, coalesced
        uint64_t d0 = dup2(f.x), d1 = dup2(f.y);
        const ulonglong2* ar = (const ulonglong2*)(awb + m*24);  // 4 broadcast LDS.128
        {
            ulonglong2 a0 = ar[0], a1 = ar[1];
            ac0[0] = ffma2(a0.x, d0, ac0[0]);  ac1[0] = ffma2(a0.x, d1, ac1[0]);
            ac0[1] = ffma2(a0.y, d0, ac0[1]);  ac1[1] = ffma2(a0.y, d1, ac1[1]);
            ac0[2] = ffma2(a1.x, d0, ac0[2]);  ac1[2] = ffma2(a1.x, d1, ac1[2]);
            ac0[3] = ffma2(a1.y, d0, ac0[3]);  ac1[3] = ffma2(a1.y, d1, ac1[3]);
        }
        {
            ulonglong2 a2 = ar[2], a3 = ar[3];
            ac0[4] = ffma2(a2.x, d0, ac0[4]);  ac1[4] = ffma2(a2.x, d1, ac1[4]);
            ac0[5] = ffma2(a2.y, d0, ac0[5]);  ac1[5] = ffma2(a2.y, d1, ac1[5]);
            ac0[6] = ffma2(a3.x, d0, ac0[6]);  ac1[6] = ffma2(a3.x, d1, ac1[6]);
            ac0[7] = ffma2(a3.y, d0, ac0[7]);  ac1[7] = ffma2(a3.y, d1, ac1[7]);
        }
    }

    // repack to WF[q][k*64 + 2*lane] (STS.64 conflict-free); k=15 is pad, skipped
    float* wr = sm + SM_WF + warp*KD;
#pragma unroll
    for (int kp = 0; kp < 7; kp++) {
        *(uint64_t*)(wr + (2*kp)*DIN   + 2*lane) = pack2(lo32(ac0[kp]), lo32(ac1[kp]));
        *(uint64_t*)(wr + (2*kp+1)*DIN + 2*lane) = pack2(hi32(ac0[kp]), hi32(ac1[kp]));
    }
    *(uint64_t*)(wr + 14*DIN + 2*lane) = pack2(lo32(ac0[7]), lo32(ac1[7]));
}

__global__ __launch_bounds__(NTHREADS, 3)
void kpconv_deform_fused(
    const float* __restrict__ qp,    // [N,3]
    const float* __restrict__ sp,    // [N,3]
    const int*   __restrict__ neigh, // [N,32]
    const float* __restrict__ x,     // [N,64]
    const float* __restrict__ kpts,  // [15,3]
    const float* __restrict__ obias, // [45]
    const float* __restrict__ w,     // [960,64]
    float*       __restrict__ out)   // [N,64]
{
    extern __shared__ float sm[];
    const int tid  = threadIdx.x;
    const int lane = tid & 31;
    const int warp = tid >> 5;
    const int h    = (lane >> 4) & 1;
    const int j    = lane & 15;
    const int q0   = blockIdx.x * QPB;
    const int q    = q0 + warp;

    if (tid < OD) sm[SM_KP + tid] = kpts[tid];

    // neighbor geometry, registers only (lane = its own neighbor m)
    float qx = qp[q*3+0], qy = qp[q*3+1], qz = qp[q*3+2];
    int   ni = neigh[q*MNB + lane];
    float nbx = sp[ni*3+0] - qx;
    float nby = sp[ni*3+1] - qy;
    float nbz = sp[ni*3+2] - qz;
    __syncthreads();

    // -------- Phase 1: rigid aggregation -> WF1 --------
    kp_aggregate(sm, warp, lane, nbx, nby, nbz, ni, sm + SM_KP, x);
    __syncthreads();

    // -------- Phase 2: offset GEMM  OF[8][48] = WF1[8][960] @ OWpad[960][48] --------
    {
        const int kk0 = (warp*2 + h) * KSL;
        uint64_t aclo[QPB], achi[QPB];
#pragma unroll
        for (int qi = 0; qi < QPB; qi++) { aclo[qi] = 0ull; achi[qi] = 0ull; }
        if (j < 12) {
            for (int kk = kk0; kk < kk0 + KSL; kk += 2) {
                ulonglong2 wA = *(const ulonglong2*)(g_owpad + kk*ODP     + 4*j);
                ulonglong2 wB = *(const ulonglong2*)(g_owpad + (kk+1)*ODP + 4*j);
#pragma unroll
                for (int qi = 0; qi < QPB; qi++) {
                    float2 f = *(const float2*)(sm + SM_WF + qi*KD + kk);  // broadcast LDS.64
                    uint64_t dx = dup2(f.x), dy = dup2(f.y);
                    aclo[qi] = ffma2(dx, wA.x, aclo[qi]);
                    achi[qi] = ffma2(dx, wA.y, achi[qi]);
                    aclo[qi] = ffma2(dy, wB.x, aclo[qi]);
                    achi[qi] = ffma2(dy, wB.y, achi[qi]);
                }
            }
        }
        __syncthreads();   // phase-1 AW reads done before P2 overlay stores
        if (j < 12) {
#pragma unroll
            for (int qi = 0; qi < QPB; qi++)
                *(ulonglong2*)(sm + SM_P2 + (warp*2 + h)*384 + qi*48 + 4*j) =
                    make_ulonglong2(aclo[qi], achi[qi]);
        }
    }
    __syncthreads();

    // reduce 16 k-slices -> OF (+bias)
    if (tid < 192) {
        int qi = tid / 24, ep = tid % 24, e = 2*ep;
        float sx = 0.f, sy = 0.f;
#pragma unroll
        for (int s = 0; s < 16; s++) {
            float2 p = *(const float2*)(sm + SM_P2 + s*384 + qi*48 + e);
            sx += p.x; sy += p.y;
        }
        sx += (e   < OD) ? obias[e]   : 0.f;
        sy += (e+1 < OD) ? obias[e+1] : 0.f;
        *(float2*)(sm + SM_OF + qi*ODP + e) = make_float2(sx, sy);
    }
    __syncthreads();

    // -------- Phase 3: deformed kernel points + aggregation -> WF2 --------
    for (int t2 = lane; t2 < OD; t2 += 32)
        sm[SM_DK + warp*ODP + t2] = sm[SM_KP + t2] + sm[SM_OF + warp*ODP + t2];
    __syncwarp();
    kp_aggregate(sm, warp, lane, nbx, nby, nbz, ni, sm + SM_DK + warp*ODP, x);
    __syncthreads();

    // -------- Phase 4: output GEMM  out[8][64] = WF2[8][960] @ W[960][64] --------
    {
        const int kk0 = (warp*2 + h) * KSL;
        uint64_t aclo[QPB], achi[QPB];
#pragma unroll
        for (int qi = 0; qi < QPB; qi++) { aclo[qi] = 0ull; achi[qi] = 0ull; }
        for (int kk = kk0; kk < kk0 + KSL; kk += 2) {
            ulonglong2 wA = *(const ulonglong2*)(w + kk*DOUT     + 4*j);
            ulonglong2 wB = *(const ulonglong2*)(w + (kk+1)*DOUT + 4*j);
#pragma unroll
            for (int qi = 0; qi < QPB; qi++) {
                float2 f = *(const float2*)(sm + SM_WF + qi*KD + kk);
                uint64_t dx = dup2(f.x), dy = dup2(f.y);
                aclo[qi] = ffma2(dx, wA.x, aclo[qi]);
                achi[qi] = ffma2(dx, wA.y, achi[qi]);
                aclo[qi] = ffma2(dy, wB.x, aclo[qi]);
                achi[qi] = ffma2(dy, wB.y, achi[qi]);
            }
        }
#pragma unroll
        for (int qi = 0; qi < QPB; qi++)
            *(ulonglong2*)(sm + SM_P4 + (warp*2 + h)*512 + qi*64 + 4*j) =
                make_ulonglong2(aclo[qi], achi[qi]);
    }
    __syncthreads();

    // reduce 16 k-slices -> global out
    {
        int qi = tid >> 5, e = (tid & 31) * 2;
        float sx = 0.f, sy = 0.f;
#pragma unroll
        for (int s = 0; s < 16; s++) {
            float2 p = *(const float2*)(sm + SM_P4 + s*512 + qi*64 + e);
            sx += p.x; sy += p.y;
        }
        *(float2*)(out + (q0 + qi)*DOUT + e) = make_float2(sx, sy);
    }
}

extern "C" void kernel_launch(void* const* d_in, const int* in_sizes, int n_in,
                              void* d_out, int out_size)
{
    const float* qp    = (const float*)d_in[0];
    const float* sp    = (const float*)d_in[1];
    const int*   neigh = (const int*)  d_in[2];
    const float* x     = (const float*)d_in[3];
    const float* kpts  = (const float*)d_in[4];
    const float* ow    = (const float*)d_in[5];
    const float* obias = (const float*)d_in[6];
    const float* w     = (const float*)d_in[7];
    float* out = (float*)d_out;

    prep_owpad<<<(KD*ODP + 255)/256, 256>>>(ow);

    cudaFuncSetAttribute(kpconv_deform_fused,
                         cudaFuncAttributeMaxDynamicSharedMemorySize, SMEM_BYTES);

    kpconv_deform_fused<<<NQ/QPB, NTHREADS, SMEM_BYTES>>>(
        qp, sp, neigh, x, kpts, obias, w, out);
}